// round 15
// baseline (speedup 1.0000x reference)
#include <cuda_runtime.h>
#include <cuda_bf16.h>
#include <cuda_fp8.h>
#include <stdint.h>

#define B_ROWS 2048
#define D_DIM  512
#define C_CLS  50000
#define BM     128
#define BN     64
#define NCB    782                 // 50048 / 64
#define C_PAD  (NCB * BN)          // 50048
#define SCALE_F  30.0f
#define MARGIN_S 9.0f

#define NWB (C_PAD / 8)            // 6256 weight prep blocks
#define NEB (B_ROWS / 8)           // 256 embedding prep blocks
#define NPREP (NEB + 1 + NWB)      // 6513 prep CTAs: [E | labels | W]
#define NGEMM (NCB * 16)           // 12512 GEMM tiles

// ---------------- scratch (device globals: allocation-free) ----------------
__device__ __align__(16) uint8_t g_Wn[(size_t)C_PAD * D_DIM];   // fp8, ~25.6 MB
__device__ __align__(16) uint8_t g_En[(size_t)B_ROWS * D_DIM];  // fp8, 1 MB
__device__ int   g_lab[B_ROWS];
__device__ float g_t[B_ROWS];
__device__ float g_ps[(size_t)B_ROWS * NCB];                    // 6.4 MB
__device__ float g_nll[B_ROWS];
__device__ int   g_ctr;                                         // k_rows last-block
__device__ int   g_flag[NPREP];                                 // prep-done flags (zero-init; k_rows resets)

__device__ __forceinline__ uint32_t smem_u32(const void* p) {
    uint32_t a;
    asm("{ .reg .u64 t; cvta.to.shared.u64 t, %1; cvt.u32.u64 %0, t; }" : "=r"(a) : "l"(p));
    return a;
}

// ---------------- fp8 helpers ----------------
__device__ __forceinline__ uint32_t pack4_fp8(float a, float b, float c, float d) {
    uint32_t lo = __nv_cvt_float2_to_fp8x2(make_float2(a, b), __NV_SATFINITE, __NV_E4M3);
    uint32_t hi = __nv_cvt_float2_to_fp8x2(make_float2(c, d), __NV_SATFINITE, __NV_E4M3);
    return lo | (hi << 16);
}

__device__ __forceinline__ void norm_row_to_fp8(const float* __restrict__ src_row,
                                                uint8_t* __restrict__ dst_row, int lane) {
    const float4* src = (const float4*)src_row;
    float4 v[4];
    float ss = 0.f;
#pragma unroll
    for (int i = 0; i < 4; i++) {
        v[i] = src[lane * 4 + i];
        ss += v[i].x * v[i].x + v[i].y * v[i].y + v[i].z * v[i].z + v[i].w * v[i].w;
    }
#pragma unroll
    for (int o = 16; o > 0; o >>= 1) ss += __shfl_xor_sync(0xffffffffu, ss, o);
    float inv = 1.0f / fmaxf(sqrtf(ss), 1e-12f);
    uint32_t p[4];
#pragma unroll
    for (int i = 0; i < 4; i++)
        p[i] = pack4_fp8(v[i].x * inv, v[i].y * inv, v[i].z * inv, v[i].w * inv);
    ((uint4*)dst_row)[lane] = make_uint4(p[0], p[1], p[2], p[3]);
}

// ---------------- GEMM primitives ----------------
__device__ __forceinline__ void mma_fp8(float c[4], const uint32_t a[4], const uint32_t b[2]) {
    asm volatile(
        "mma.sync.aligned.m16n8k32.row.col.f32.e4m3.e4m3.f32 "
        "{%0,%1,%2,%3}, {%4,%5,%6,%7}, {%8,%9}, {%0,%1,%2,%3};\n"
        : "+f"(c[0]), "+f"(c[1]), "+f"(c[2]), "+f"(c[3])
        : "r"(a[0]), "r"(a[1]), "r"(a[2]), "r"(a[3]), "r"(b[0]), "r"(b[1]));
}
__device__ __forceinline__ void ldsm4(uint32_t* r, uint32_t addr) {
    asm volatile("ldmatrix.sync.aligned.m8n8.x4.shared.b16 {%0,%1,%2,%3}, [%4];"
                 : "=r"(r[0]), "=r"(r[1]), "=r"(r[2]), "=r"(r[3]) : "r"(addr));
}

// Block 128x64, 8 warps (4 row x 2 col), warp tile 32x32.
// 3-stage BK=64 pipeline. Stage s: A at s*15360 (128x80), B at s*15360+10240 (64x80).
#define ST_SZ   15360
#define OFF_BB  10240
#define OFF_LAB 46080
#define OFF_RED 46592
#define DSMEM   (OFF_RED + 1024)

extern __shared__ uint8_t dsm[];

__device__ __forceinline__ void fill_tile(uint32_t sA, const uint8_t* Af,
                                          const uint8_t* Bf, int kb) {
#pragma unroll
    for (int i = 0; i < 2; i++) {      // A: 128 rows, 2 per thread
        asm volatile("cp.async.cg.shared.global [%0], [%1], 16;"
                     :: "r"(sA + i * (64 * 80)), "l"(Af + kb + (size_t)i * 64 * D_DIM));
    }
    asm volatile("cp.async.cg.shared.global [%0], [%1], 16;"   // B: 64 rows, 1 per thread
                 :: "r"(sA + OFF_BB), "l"(Bf + kb));
}

// ---------------- mega kernel: prep CTAs (bid < NPREP) then GEMM tiles ----------------
__global__ __launch_bounds__(256, 3) void k_mega(const float* __restrict__ W,
                                                 const float* __restrict__ E,
                                                 const int* __restrict__ lab32) {
    const int bid = blockIdx.x;
    const int tid = threadIdx.x;
    const int lane = tid & 31;

    if (bid < NPREP) {
        // ---------- prep: [E blocks | labels | W blocks], publish flag when done ----------
        if (bid < NEB) {                           // embedding rows
            int row = bid * 8 + (tid >> 5);
            norm_row_to_fp8(E + (size_t)row * D_DIM, g_En + (size_t)row * D_DIM, lane);
        } else if (bid == NEB) {                   // labels: sniff int64 vs int32
            int local = 0;
#pragma unroll
            for (int k = 0; k < 4; k++)
                if (lab32[2 * (tid * 4 + k) + 1] != 0) local = 1;
            if (__syncthreads_or(local)) {
                for (int j = tid; j < B_ROWS; j += 256) g_lab[j] = lab32[j];
            } else {
                for (int j = tid; j < B_ROWS; j += 256) g_lab[j] = lab32[2 * j];
            }
        } else {                                   // weight rows
            int row = (bid - NEB - 1) * 8 + (tid >> 5);
            uint8_t* dst = g_Wn + (size_t)row * D_DIM;
            if (row >= C_CLS) ((uint4*)dst)[lane] = make_uint4(0, 0, 0, 0);
            else              norm_row_to_fp8(W + (size_t)row * D_DIM, dst, lane);
        }
        __syncthreads();
        __threadfence();
        if (tid == 0) *((volatile int*)&g_flag[bid]) = 1;
        return;
    }

    // ---------- GEMM tile ----------
    const int t  = bid - NPREP;
    const int cb = t % NCB, by = t / NCB;
    const int warp = tid >> 5;
    const int wr = warp & 3, wc = warp >> 2;
    const int row0 = by * BM, col0 = cb * BN;

    // acquire: 8 W-blocks, 16 E-blocks, labels
    if (tid < 25) {
        int fi;
        if (tid < 8)       fi = NEB + 1 + cb * 8 + tid;       // W blocks for cols [cb*64, +64)
        else if (tid < 24) fi = by * 16 + (tid - 8);          // E blocks for rows [by*128, +128)
        else               fi = NEB;                          // labels
        while (*((volatile int*)&g_flag[fi]) == 0) { }
    }
    __syncthreads();

    const uint32_t sbase = smem_u32(dsm);
    int*   slab  = (int*)(dsm + OFF_LAB);
    float (*red_s)[2] = (float(*)[2])(dsm + OFF_RED);

    if (tid < 128) slab[tid] = __ldcg(&g_lab[row0 + tid]);

    // per-thread fill bases (row tid>>2, 16B chunk tid&3)
    const int fr = tid >> 2, fc = (tid & 3) * 16;
    const uint8_t* Af = g_En + (size_t)(row0 + fr) * D_DIM + fc;
    const uint8_t* Bf = g_Wn + (size_t)(col0 + fr) * D_DIM + fc;
    const uint32_t smA = (uint32_t)(fr * 80 + fc);

    float acc[2][4][4];
#pragma unroll
    for (int i = 0; i < 2; i++)
#pragma unroll
        for (int j = 0; j < 4; j++)
#pragma unroll
            for (int k = 0; k < 4; k++) acc[i][j][k] = 0.f;

    // per-lane ldmatrix base offsets (quad q = lane>>3, lr = lane&7)
    const int q = lane >> 3, lr = lane & 7;
    const uint32_t offA = (uint32_t)(((q & 1) * 8 + lr) * 80 + (q >> 1) * 16);
    const uint32_t offB = (uint32_t)(((q >> 1) * 8 + lr) * 80 + (q & 1) * 16);

    // prologue: stages 0,1
    fill_tile(sbase + smA, Af, Bf, 0);
    asm volatile("cp.async.commit_group;" ::: "memory");
    fill_tile(sbase + ST_SZ + smA, Af, Bf, 64);
    asm volatile("cp.async.commit_group;" ::: "memory");

#pragma unroll
    for (int kt = 0; kt < 8; kt++) {
        const int st = kt % 3;
        if (kt < 7) asm volatile("cp.async.wait_group 1;" ::: "memory");
        else        asm volatile("cp.async.wait_group 0;" ::: "memory");
        __syncthreads();
        if (kt < 6) {
            fill_tile(sbase + ((kt + 2) % 3) * ST_SZ + smA, Af, Bf, (kt + 2) * 64);
            asm volatile("cp.async.commit_group;" ::: "memory");
        }
        const uint32_t aBase = sbase + st * ST_SZ + (uint32_t)(wr * 2560) + offA;
        const uint32_t bBase = sbase + st * ST_SZ + OFF_BB + (uint32_t)(wc * 2560) + offB;
#pragma unroll
        for (int ks = 0; ks < 2; ks++) {
            uint32_t afr[2][4], bfr[4][2];
#pragma unroll
            for (int mi = 0; mi < 2; mi++)
                ldsm4(afr[mi], aBase + ks * 32 + mi * 1280);
            uint32_t bt[4];
            ldsm4(bt, bBase + ks * 32);
            bfr[0][0] = bt[0]; bfr[0][1] = bt[1]; bfr[1][0] = bt[2]; bfr[1][1] = bt[3];
            ldsm4(bt, bBase + ks * 32 + 1280);
            bfr[2][0] = bt[0]; bfr[2][1] = bt[1]; bfr[3][0] = bt[2]; bfr[3][1] = bt[3];
#pragma unroll
            for (int mi = 0; mi < 2; mi++)
#pragma unroll
                for (int nf = 0; nf < 4; nf++)
                    mma_fp8(acc[mi][nf], afr[mi], bfr[nf]);
        }
    }

    // Epilogue: logits = 30*cos (-9 at label); fixed max 30 -> partial sum-exp.
#pragma unroll
    for (int mi = 0; mi < 2; mi++) {
#pragma unroll
        for (int h = 0; h < 2; h++) {
            int rloc = wr * 32 + mi * 16 + h * 8 + (lane >> 2);
            int lab = slab[rloc];
            float s = 0.f;
#pragma unroll
            for (int nf = 0; nf < 4; nf++) {
#pragma unroll
                for (int j = 0; j < 2; j++) {
                    int cg = col0 + wc * 32 + nf * 8 + (lane & 3) * 2 + j;
                    float v = acc[mi][nf][h * 2 + j] * SCALE_F;
                    if (cg == lab) { v -= MARGIN_S; g_t[row0 + rloc] = v; }
                    if (cg < C_CLS) s += __expf(v - 30.0f);
                }
            }
            s += __shfl_xor_sync(0xffffffffu, s, 1);
            s += __shfl_xor_sync(0xffffffffu, s, 2);
            if ((lane & 3) == 0) red_s[rloc][wc] = s;
        }
    }
    __syncthreads();
    if (tid < 128) {
        float S = red_s[tid][0] + red_s[tid][1];
        g_ps[(size_t)(row0 + tid) * NCB + cb] = S;
    }
}

// ---------------- per-row combine -> nll; last block means; flags reset ----------------
__global__ __launch_bounds__(256) void k_rows(float* __restrict__ out) {
    int row  = blockIdx.x * 8 + (threadIdx.x >> 5);
    int lane = threadIdx.x & 31;
    {
        const float* ps = g_ps + (size_t)row * NCB;
        float s = 0.f;
        for (int i = lane; i < NCB; i += 32) s += ps[i];
#pragma unroll
        for (int o = 16; o > 0; o >>= 1) s += __shfl_xor_sync(0xffffffffu, s, o);
        if (lane == 0) g_nll[row] = 30.0f + logf(s) - g_t[row];
    }
    // reset prep flags for next graph replay (GEMM is complete by stream order)
    if (blockIdx.x == 0) {
        for (int i = threadIdx.x; i < NPREP; i += 256) g_flag[i] = 0;
    }
    // last-block mean (deterministic: single block sums in fixed order)
    __shared__ bool last;
    __threadfence();
    __syncthreads();
    if (threadIdx.x == 0) last = (atomicAdd(&g_ctr, 1) == (int)gridDim.x - 1);
    __syncthreads();
    if (last) {
        __shared__ float sh[256];
        float s = 0.f;
        for (int i = threadIdx.x; i < B_ROWS; i += 256) s += g_nll[i];
        sh[threadIdx.x] = s;
        __syncthreads();
        for (int o = 128; o > 0; o >>= 1) {
            if (threadIdx.x < o) sh[threadIdx.x] += sh[threadIdx.x + o];
            __syncthreads();
        }
        if (threadIdx.x == 0) { out[0] = sh[0] * (1.0f / B_ROWS); g_ctr = 0; }
    }
}

// ---------------- launch ----------------
extern "C" void kernel_launch(void* const* d_in, const int* in_sizes, int n_in,
                              void* d_out, int out_size) {
    const float* emb   = (const float*)d_in[0];
    const int*   lab32 = (const int*)d_in[1];
    const float* W     = (const float*)d_in[2];
    float* out = (float*)d_out;

    cudaFuncSetAttribute(k_mega, cudaFuncAttributeMaxDynamicSharedMemorySize, DSMEM);

    k_mega<<<NPREP + NGEMM, 256, DSMEM>>>(W, emb, lab32);
    k_rows<<<B_ROWS / 8, 256>>>(out);
}

// round 16
// speedup vs baseline: 1.0333x; 1.0333x over previous
#include <cuda_runtime.h>
#include <cuda_bf16.h>
#include <cuda_fp8.h>
#include <stdint.h>

#define B_ROWS 2048
#define D_DIM  512
#define C_CLS  50000
#define BM     128
#define BN     64
#define NCB    782                 // 50048 / 64
#define PSS    784                 // padded partial stride (16B-aligned rows; pads stay 0)
#define C_PAD  (NCB * BN)          // 50048
#define SCALE_F  30.0f
#define MARGIN_S 9.0f

#define NWB (C_PAD / 8)            // 6256 weight blocks
#define NEB (B_ROWS / 8)           // 256 embedding blocks

// ---------------- scratch (device globals: allocation-free) ----------------
__device__ __align__(16) uint8_t g_Wn[(size_t)C_PAD * D_DIM];   // fp8, ~25.6 MB
__device__ __align__(16) uint8_t g_En[(size_t)B_ROWS * D_DIM];  // fp8, 1 MB
__device__ int   g_lab[B_ROWS];
__device__ float g_t[B_ROWS];
__device__ __align__(16) float g_ps[(size_t)B_ROWS * PSS];      // 6.4 MB (pad cols never written)
__device__ float g_nll[B_ROWS];
__device__ int   g_ctr;                                         // zero-init; reset each call

__device__ __forceinline__ uint32_t smem_u32(const void* p) {
    uint32_t a;
    asm("{ .reg .u64 t; cvta.to.shared.u64 t, %1; cvt.u32.u64 %0, t; }" : "=r"(a) : "l"(p));
    return a;
}

// ---------------- fused prep: W-normalize | E-normalize | labels ----------------
__device__ __forceinline__ uint32_t pack4_fp8(float a, float b, float c, float d) {
    uint32_t lo = __nv_cvt_float2_to_fp8x2(make_float2(a, b), __NV_SATFINITE, __NV_E4M3);
    uint32_t hi = __nv_cvt_float2_to_fp8x2(make_float2(c, d), __NV_SATFINITE, __NV_E4M3);
    return lo | (hi << 16);
}

__device__ __forceinline__ void norm_row_to_fp8(const float* __restrict__ src_row,
                                                uint8_t* __restrict__ dst_row, int lane) {
    const float4* src = (const float4*)src_row;
    float4 v[4];
    float ss = 0.f;
#pragma unroll
    for (int i = 0; i < 4; i++) {
        v[i] = src[lane * 4 + i];
        ss += v[i].x * v[i].x + v[i].y * v[i].y + v[i].z * v[i].z + v[i].w * v[i].w;
    }
#pragma unroll
    for (int o = 16; o > 0; o >>= 1) ss += __shfl_xor_sync(0xffffffffu, ss, o);
    float inv = 1.0f / fmaxf(sqrtf(ss), 1e-12f);
    uint32_t p[4];
#pragma unroll
    for (int i = 0; i < 4; i++)
        p[i] = pack4_fp8(v[i].x * inv, v[i].y * inv, v[i].z * inv, v[i].w * inv);
    ((uint4*)dst_row)[lane] = make_uint4(p[0], p[1], p[2], p[3]);
}

__global__ __launch_bounds__(256) void k_prep(const float* __restrict__ W,
                                              const float* __restrict__ E,
                                              const int* __restrict__ lab32) {
    const int bid = blockIdx.x;
    const int lane = threadIdx.x & 31;
    if (bid < NWB) {                               // weight rows
        int row = bid * 8 + (threadIdx.x >> 5);
        uint8_t* dst = g_Wn + (size_t)row * D_DIM;
        if (row >= C_CLS) { ((uint4*)dst)[lane] = make_uint4(0, 0, 0, 0); return; }
        norm_row_to_fp8(W + (size_t)row * D_DIM, dst, lane);
    } else if (bid < NWB + NEB) {                  // embedding rows
        int row = (bid - NWB) * 8 + (threadIdx.x >> 5);
        norm_row_to_fp8(E + (size_t)row * D_DIM, g_En + (size_t)row * D_DIM, lane);
    } else {                                       // labels: sniff int64 vs int32
        int local = 0;
#pragma unroll
        for (int k = 0; k < 4; k++)
            if (lab32[2 * (threadIdx.x * 4 + k) + 1] != 0) local = 1;
        if (__syncthreads_or(local)) {             // int32 layout
            for (int j = threadIdx.x; j < B_ROWS; j += 256) g_lab[j] = lab32[j];
        } else {                                   // int64 layout (hi words all zero)
            for (int j = threadIdx.x; j < B_ROWS; j += 256) g_lab[j] = lab32[2 * j];
        }
    }
}

// ---------------- fp8 MMA GEMM + fused partial softmax ----------------
__device__ __forceinline__ void mma_fp8(float c[4], const uint32_t a[4], const uint32_t b[2]) {
    asm volatile(
        "mma.sync.aligned.m16n8k32.row.col.f32.e4m3.e4m3.f32 "
        "{%0,%1,%2,%3}, {%4,%5,%6,%7}, {%8,%9}, {%0,%1,%2,%3};\n"
        : "+f"(c[0]), "+f"(c[1]), "+f"(c[2]), "+f"(c[3])
        : "r"(a[0]), "r"(a[1]), "r"(a[2]), "r"(a[3]), "r"(b[0]), "r"(b[1]));
}
__device__ __forceinline__ void ldsm4(uint32_t* r, uint32_t addr) {
    asm volatile("ldmatrix.sync.aligned.m8n8.x4.shared.b16 {%0,%1,%2,%3}, [%4];"
                 : "=r"(r[0]), "=r"(r[1]), "=r"(r[2]), "=r"(r[3]) : "r"(addr));
}

// Block 128x64, 8 warps (4 row x 2 col), warp tile 32x32.
// 3-stage BK=64 pipeline. Stage s: A at s*15360 (128x80), B at s*15360+10240 (64x80).
#define ST_SZ   15360
#define OFF_BB  10240
#define OFF_LAB 46080
#define OFF_RED 46592
#define DSMEM   (OFF_RED + 1024)

extern __shared__ uint8_t dsm[];

__device__ __forceinline__ void fill_tile(uint32_t sA, const uint8_t* Af,
                                          const uint8_t* Bf, int kb) {
#pragma unroll
    for (int i = 0; i < 2; i++) {      // A: 128 rows, 2 per thread
        asm volatile("cp.async.cg.shared.global [%0], [%1], 16;"
                     :: "r"(sA + i * (64 * 80)), "l"(Af + kb + (size_t)i * 64 * D_DIM));
    }
    asm volatile("cp.async.cg.shared.global [%0], [%1], 16;"   // B: 64 rows, 1 per thread
                 :: "r"(sA + OFF_BB), "l"(Bf + kb));
}

__global__ __launch_bounds__(256, 3) void k_gemm() {
    const int cb = blockIdx.x, by = blockIdx.y;
    const int tid = threadIdx.x;
    const int lane = tid & 31, warp = tid >> 5;
    const int wr = warp & 3, wc = warp >> 2;
    const int row0 = by * BM, col0 = cb * BN;

    const uint32_t sbase = smem_u32(dsm);
    int*   slab  = (int*)(dsm + OFF_LAB);
    float (*red_s)[2] = (float(*)[2])(dsm + OFF_RED);

    if (tid < 128) slab[tid] = g_lab[row0 + tid];

    // per-thread fill bases (row tid>>2, 16B chunk tid&3)
    const int fr = tid >> 2, fc = (tid & 3) * 16;
    const uint8_t* Af = g_En + (size_t)(row0 + fr) * D_DIM + fc;
    const uint8_t* Bf = g_Wn + (size_t)(col0 + fr) * D_DIM + fc;
    const uint32_t smA = (uint32_t)(fr * 80 + fc);

    float acc[2][4][4];
#pragma unroll
    for (int i = 0; i < 2; i++)
#pragma unroll
        for (int j = 0; j < 4; j++)
#pragma unroll
            for (int k = 0; k < 4; k++) acc[i][j][k] = 0.f;

    // per-lane ldmatrix base offsets (quad q = lane>>3, lr = lane&7)
    const int q = lane >> 3, lr = lane & 7;
    const uint32_t offA = (uint32_t)(((q & 1) * 8 + lr) * 80 + (q >> 1) * 16);
    const uint32_t offB = (uint32_t)(((q >> 1) * 8 + lr) * 80 + (q & 1) * 16);

    // prologue: stages 0,1
    fill_tile(sbase + smA, Af, Bf, 0);
    asm volatile("cp.async.commit_group;" ::: "memory");
    fill_tile(sbase + ST_SZ + smA, Af, Bf, 64);
    asm volatile("cp.async.commit_group;" ::: "memory");

#pragma unroll
    for (int kt = 0; kt < 8; kt++) {
        const int st = kt % 3;
        if (kt < 7) asm volatile("cp.async.wait_group 1;" ::: "memory");
        else        asm volatile("cp.async.wait_group 0;" ::: "memory");
        __syncthreads();
        if (kt < 6) {
            fill_tile(sbase + ((kt + 2) % 3) * ST_SZ + smA, Af, Bf, (kt + 2) * 64);
            asm volatile("cp.async.commit_group;" ::: "memory");
        }
        const uint32_t aBase = sbase + st * ST_SZ + (uint32_t)(wr * 2560) + offA;
        const uint32_t bBase = sbase + st * ST_SZ + OFF_BB + (uint32_t)(wc * 2560) + offB;
#pragma unroll
        for (int ks = 0; ks < 2; ks++) {
            uint32_t afr[2][4], bfr[4][2];
#pragma unroll
            for (int mi = 0; mi < 2; mi++)
                ldsm4(afr[mi], aBase + ks * 32 + mi * 1280);
            uint32_t bt[4];
            ldsm4(bt, bBase + ks * 32);
            bfr[0][0] = bt[0]; bfr[0][1] = bt[1]; bfr[1][0] = bt[2]; bfr[1][1] = bt[3];
            ldsm4(bt, bBase + ks * 32 + 1280);
            bfr[2][0] = bt[0]; bfr[2][1] = bt[1]; bfr[3][0] = bt[2]; bfr[3][1] = bt[3];
#pragma unroll
            for (int mi = 0; mi < 2; mi++)
#pragma unroll
                for (int nf = 0; nf < 4; nf++)
                    mma_fp8(acc[mi][nf], afr[mi], bfr[nf]);
        }
    }

    // Epilogue: logits = 30*cos (-9 at label); fixed max 30 -> partial sum-exp.
#pragma unroll
    for (int mi = 0; mi < 2; mi++) {
#pragma unroll
        for (int h = 0; h < 2; h++) {
            int rloc = wr * 32 + mi * 16 + h * 8 + (lane >> 2);
            int lab = slab[rloc];
            float s = 0.f;
#pragma unroll
            for (int nf = 0; nf < 4; nf++) {
#pragma unroll
                for (int j = 0; j < 2; j++) {
                    int cg = col0 + wc * 32 + nf * 8 + (lane & 3) * 2 + j;
                    float v = acc[mi][nf][h * 2 + j] * SCALE_F;
                    if (cg == lab) { v -= MARGIN_S; g_t[row0 + rloc] = v; }
                    if (cg < C_CLS) s += __expf(v - 30.0f);
                }
            }
            s += __shfl_xor_sync(0xffffffffu, s, 1);
            s += __shfl_xor_sync(0xffffffffu, s, 2);
            if ((lane & 3) == 0) red_s[rloc][wc] = s;
        }
    }
    __syncthreads();
    if (tid < 128) {
        float S = red_s[tid][0] + red_s[tid][1];
        g_ps[(size_t)(row0 + tid) * PSS + cb] = S;
    }
}

// ---------------- per-row combine (float4) -> nll; last block computes the mean ----------------
__global__ __launch_bounds__(256) void k_rows(float* __restrict__ out) {
    int row  = blockIdx.x * 8 + (threadIdx.x >> 5);
    int lane = threadIdx.x & 31;
    {
        const float4* ps = (const float4*)(g_ps + (size_t)row * PSS);
        float s = 0.f;
#pragma unroll 1
        for (int i = lane; i < PSS / 4; i += 32) {
            float4 v = ps[i];
            s += (v.x + v.y) + (v.z + v.w);        // pad cols are 0 (never written)
        }
#pragma unroll
        for (int o = 16; o > 0; o >>= 1) s += __shfl_xor_sync(0xffffffffu, s, o);
        if (lane == 0) g_nll[row] = 30.0f + logf(s) - g_t[row];
    }
    // last-block mean (deterministic: single block sums in fixed order)
    __shared__ bool last;
    __threadfence();
    __syncthreads();
    if (threadIdx.x == 0) last = (atomicAdd(&g_ctr, 1) == (int)gridDim.x - 1);
    __syncthreads();
    if (last) {
        __shared__ float sh[256];
        float s = 0.f;
        for (int i = threadIdx.x; i < B_ROWS; i += 256) s += g_nll[i];
        sh[threadIdx.x] = s;
        __syncthreads();
        for (int o = 128; o > 0; o >>= 1) {
            if (threadIdx.x < o) sh[threadIdx.x] += sh[threadIdx.x + o];
            __syncthreads();
        }
        if (threadIdx.x == 0) { out[0] = sh[0] * (1.0f / B_ROWS); g_ctr = 0; }
    }
}

// ---------------- launch ----------------
extern "C" void kernel_launch(void* const* d_in, const int* in_sizes, int n_in,
                              void* d_out, int out_size) {
    const float* emb   = (const float*)d_in[0];
    const int*   lab32 = (const int*)d_in[1];
    const float* W     = (const float*)d_in[2];
    float* out = (float*)d_out;

    cudaFuncSetAttribute(k_gemm, cudaFuncAttributeMaxDynamicSharedMemorySize, DSMEM);

    k_prep<<<NWB + NEB + 1, 256>>>(W, emb, lab32);
    k_gemm<<<dim3(NCB, B_ROWS / BM), 256, DSMEM>>>();
    k_rows<<<B_ROWS / 8, 256>>>(out);
}

// round 17
// speedup vs baseline: 1.0385x; 1.0051x over previous
#include <cuda_runtime.h>
#include <cuda_bf16.h>
#include <cuda_fp8.h>
#include <stdint.h>

#define B_ROWS 2048
#define D_DIM  512
#define C_CLS  50000
#define BM     128
#define BN     64
#define NCB    782                 // 50048 / 64
#define C_PAD  (NCB * BN)          // 50048
#define SCALE_F  30.0f
#define MARGIN_S 9.0f

#define NWB (C_PAD / 8)            // 6256 weight blocks
#define NEB (B_ROWS / 8)           // 256 embedding blocks

// ---------------- scratch (device globals: allocation-free) ----------------
__device__ __align__(16) uint8_t g_Wn[(size_t)C_PAD * D_DIM];   // fp8, ~25.6 MB
__device__ __align__(16) uint8_t g_En[(size_t)B_ROWS * D_DIM];  // fp8, 1 MB
__device__ int   g_lab[B_ROWS];
__device__ float g_t[B_ROWS];
__device__ float g_ps[(size_t)B_ROWS * NCB];                    // 6.4 MB
__device__ float g_nll[B_ROWS];
__device__ int   g_ctr;                                         // zero-init; reset each call

__device__ __forceinline__ uint32_t smem_u32(const void* p) {
    uint32_t a;
    asm("{ .reg .u64 t; cvta.to.shared.u64 t, %1; cvt.u32.u64 %0, t; }" : "=r"(a) : "l"(p));
    return a;
}

// ---------------- fused prep: W-normalize | E-normalize | labels ----------------
__device__ __forceinline__ uint32_t pack4_fp8(float a, float b, float c, float d) {
    uint32_t lo = __nv_cvt_float2_to_fp8x2(make_float2(a, b), __NV_SATFINITE, __NV_E4M3);
    uint32_t hi = __nv_cvt_float2_to_fp8x2(make_float2(c, d), __NV_SATFINITE, __NV_E4M3);
    return lo | (hi << 16);
}

__device__ __forceinline__ void norm_row_to_fp8(const float* __restrict__ src_row,
                                                uint8_t* __restrict__ dst_row, int lane) {
    const float4* src = (const float4*)src_row;
    float4 v[4];
    float ss = 0.f;
#pragma unroll
    for (int i = 0; i < 4; i++) {
        v[i] = src[lane * 4 + i];
        ss += v[i].x * v[i].x + v[i].y * v[i].y + v[i].z * v[i].z + v[i].w * v[i].w;
    }
#pragma unroll
    for (int o = 16; o > 0; o >>= 1) ss += __shfl_xor_sync(0xffffffffu, ss, o);
    float inv = 1.0f / fmaxf(sqrtf(ss), 1e-12f);
    uint32_t p[4];
#pragma unroll
    for (int i = 0; i < 4; i++)
        p[i] = pack4_fp8(v[i].x * inv, v[i].y * inv, v[i].z * inv, v[i].w * inv);
    ((uint4*)dst_row)[lane] = make_uint4(p[0], p[1], p[2], p[3]);
}

__global__ __launch_bounds__(256) void k_prep(const float* __restrict__ W,
                                              const float* __restrict__ E,
                                              const int* __restrict__ lab32) {
    const int bid = blockIdx.x;
    const int lane = threadIdx.x & 31;
    if (bid < NWB) {                               // weight rows
        int row = bid * 8 + (threadIdx.x >> 5);
        uint8_t* dst = g_Wn + (size_t)row * D_DIM;
        if (row >= C_CLS) { ((uint4*)dst)[lane] = make_uint4(0, 0, 0, 0); return; }
        norm_row_to_fp8(W + (size_t)row * D_DIM, dst, lane);
    } else if (bid < NWB + NEB) {                  // embedding rows
        int row = (bid - NWB) * 8 + (threadIdx.x >> 5);
        norm_row_to_fp8(E + (size_t)row * D_DIM, g_En + (size_t)row * D_DIM, lane);
    } else {                                       // labels: sniff int64 vs int32
        int local = 0;
#pragma unroll
        for (int k = 0; k < 4; k++)
            if (lab32[2 * (threadIdx.x * 4 + k) + 1] != 0) local = 1;
        if (__syncthreads_or(local)) {             // int32 layout
            for (int j = threadIdx.x; j < B_ROWS; j += 256) g_lab[j] = lab32[j];
        } else {                                   // int64 layout (hi words all zero)
            for (int j = threadIdx.x; j < B_ROWS; j += 256) g_lab[j] = lab32[2 * j];
        }
    }
}

// ---------------- fp8 MMA GEMM + fused partial softmax ----------------
__device__ __forceinline__ void mma_fp8(float c[4], const uint32_t a[4], const uint32_t b[2]) {
    asm volatile(
        "mma.sync.aligned.m16n8k32.row.col.f32.e4m3.e4m3.f32 "
        "{%0,%1,%2,%3}, {%4,%5,%6,%7}, {%8,%9}, {%0,%1,%2,%3};\n"
        : "+f"(c[0]), "+f"(c[1]), "+f"(c[2]), "+f"(c[3])
        : "r"(a[0]), "r"(a[1]), "r"(a[2]), "r"(a[3]), "r"(b[0]), "r"(b[1]));
}
__device__ __forceinline__ void ldsm4(uint32_t* r, uint32_t addr) {
    asm volatile("ldmatrix.sync.aligned.m8n8.x4.shared.b16 {%0,%1,%2,%3}, [%4];"
                 : "=r"(r[0]), "=r"(r[1]), "=r"(r[2]), "=r"(r[3]) : "r"(addr));
}

// Block 128x64, 8 warps (4 row x 2 col), warp tile 32x32.
// 3-stage BK=64 pipeline. Stage s: A at s*15360 (128x80), B at s*15360+10240 (64x80).
#define ST_SZ   15360
#define OFF_BB  10240
#define OFF_LAB 46080
#define OFF_RED 46592
#define DSMEM   (OFF_RED + 1024)

extern __shared__ uint8_t dsm[];

__device__ __forceinline__ void fill_tile(uint32_t sA, const uint8_t* Af,
                                          const uint8_t* Bf, int kb) {
#pragma unroll
    for (int i = 0; i < 2; i++) {      // A: 128 rows, 2 per thread
        asm volatile("cp.async.cg.shared.global [%0], [%1], 16;"
                     :: "r"(sA + i * (64 * 80)), "l"(Af + kb + (size_t)i * 64 * D_DIM));
    }
    asm volatile("cp.async.cg.shared.global [%0], [%1], 16;"   // B: 64 rows, 1 per thread
                 :: "r"(sA + OFF_BB), "l"(Bf + kb));
}

__global__ __launch_bounds__(256, 3) void k_gemm() {
    const int cb = blockIdx.x, by = blockIdx.y;
    const int tid = threadIdx.x;
    const int lane = tid & 31, warp = tid >> 5;
    const int wr = warp & 3, wc = warp >> 2;
    const int row0 = by * BM, col0 = cb * BN;

    const uint32_t sbase = smem_u32(dsm);
    int*   slab  = (int*)(dsm + OFF_LAB);
    float (*red_s)[2] = (float(*)[2])(dsm + OFF_RED);

    if (tid < 128) slab[tid] = g_lab[row0 + tid];

    // per-thread fill bases (row tid>>2, 16B chunk tid&3)
    const int fr = tid >> 2, fc = (tid & 3) * 16;
    const uint8_t* Af = g_En + (size_t)(row0 + fr) * D_DIM + fc;
    const uint8_t* Bf = g_Wn + (size_t)(col0 + fr) * D_DIM + fc;
    const uint32_t smA = (uint32_t)(fr * 80 + fc);

    float acc[2][4][4];
#pragma unroll
    for (int i = 0; i < 2; i++)
#pragma unroll
        for (int j = 0; j < 4; j++)
#pragma unroll
            for (int k = 0; k < 4; k++) acc[i][j][k] = 0.f;

    // per-lane ldmatrix base offsets (quad q = lane>>3, lr = lane&7)
    const int q = lane >> 3, lr = lane & 7;
    const uint32_t offA = (uint32_t)(((q & 1) * 8 + lr) * 80 + (q >> 1) * 16);
    const uint32_t offB = (uint32_t)(((q >> 1) * 8 + lr) * 80 + (q & 1) * 16);

    // prologue: stages 0,1
    fill_tile(sbase + smA, Af, Bf, 0);
    asm volatile("cp.async.commit_group;" ::: "memory");
    fill_tile(sbase + ST_SZ + smA, Af, Bf, 64);
    asm volatile("cp.async.commit_group;" ::: "memory");

#pragma unroll
    for (int kt = 0; kt < 8; kt++) {
        const int st = kt % 3;
        if (kt < 7) asm volatile("cp.async.wait_group 1;" ::: "memory");
        else        asm volatile("cp.async.wait_group 0;" ::: "memory");
        __syncthreads();
        if (kt < 6) {
            fill_tile(sbase + ((kt + 2) % 3) * ST_SZ + smA, Af, Bf, (kt + 2) * 64);
            asm volatile("cp.async.commit_group;" ::: "memory");
        }
        const uint32_t aBase = sbase + st * ST_SZ + (uint32_t)(wr * 2560) + offA;
        const uint32_t bBase = sbase + st * ST_SZ + OFF_BB + (uint32_t)(wc * 2560) + offB;
#pragma unroll
        for (int ks = 0; ks < 2; ks++) {
            uint32_t afr[2][4], bfr[4][2];
#pragma unroll
            for (int mi = 0; mi < 2; mi++)
                ldsm4(afr[mi], aBase + ks * 32 + mi * 1280);
            uint32_t bt[4];
            ldsm4(bt, bBase + ks * 32);
            bfr[0][0] = bt[0]; bfr[0][1] = bt[1]; bfr[1][0] = bt[2]; bfr[1][1] = bt[3];
            ldsm4(bt, bBase + ks * 32 + 1280);
            bfr[2][0] = bt[0]; bfr[2][1] = bt[1]; bfr[3][0] = bt[2]; bfr[3][1] = bt[3];
#pragma unroll
            for (int mi = 0; mi < 2; mi++)
#pragma unroll
                for (int nf = 0; nf < 4; nf++)
                    mma_fp8(acc[mi][nf], afr[mi], bfr[nf]);
        }
    }

    // Epilogue: logits = 30*cos (-9 at label); fixed max 30 -> partial sum-exp.
#pragma unroll
    for (int mi = 0; mi < 2; mi++) {
#pragma unroll
        for (int h = 0; h < 2; h++) {
            int rloc = wr * 32 + mi * 16 + h * 8 + (lane >> 2);
            int lab = slab[rloc];
            float s = 0.f;
#pragma unroll
            for (int nf = 0; nf < 4; nf++) {
#pragma unroll
                for (int j = 0; j < 2; j++) {
                    int cg = col0 + wc * 32 + nf * 8 + (lane & 3) * 2 + j;
                    float v = acc[mi][nf][h * 2 + j] * SCALE_F;
                    if (cg == lab) { v -= MARGIN_S; g_t[row0 + rloc] = v; }
                    if (cg < C_CLS) s += __expf(v - 30.0f);
                }
            }
            s += __shfl_xor_sync(0xffffffffu, s, 1);
            s += __shfl_xor_sync(0xffffffffu, s, 2);
            if ((lane & 3) == 0) red_s[rloc][wc] = s;
        }
    }
    __syncthreads();
    if (tid < 128) {
        float S = red_s[tid][0] + red_s[tid][1];
        g_ps[(size_t)(row0 + tid) * NCB + cb] = S;
    }
}

// ---------------- per-row combine -> nll; last block computes the mean ----------------
__global__ __launch_bounds__(256) void k_rows(float* __restrict__ out) {
    int row  = blockIdx.x * 8 + (threadIdx.x >> 5);
    int lane = threadIdx.x & 31;
    {
        const float* ps = g_ps + (size_t)row * NCB;
        float s = 0.f;
        for (int i = lane; i < NCB; i += 32) s += ps[i];
#pragma unroll
        for (int o = 16; o > 0; o >>= 1) s += __shfl_xor_sync(0xffffffffu, s, o);
        if (lane == 0) g_nll[row] = 30.0f + logf(s) - g_t[row];
    }
    // last-block mean (deterministic: single block sums in fixed order)
    __shared__ bool last;
    __threadfence();
    __syncthreads();
    if (threadIdx.x == 0) last = (atomicAdd(&g_ctr, 1) == (int)gridDim.x - 1);
    __syncthreads();
    if (last) {
        __shared__ float sh[256];
        float s = 0.f;
        for (int i = threadIdx.x; i < B_ROWS; i += 256) s += g_nll[i];
        sh[threadIdx.x] = s;
        __syncthreads();
        for (int o = 128; o > 0; o >>= 1) {
            if (threadIdx.x < o) sh[threadIdx.x] += sh[threadIdx.x + o];
            __syncthreads();
        }
        if (threadIdx.x == 0) { out[0] = sh[0] * (1.0f / B_ROWS); g_ctr = 0; }
    }
}

// ---------------- launch ----------------
extern "C" void kernel_launch(void* const* d_in, const int* in_sizes, int n_in,
                              void* d_out, int out_size) {
    const float* emb   = (const float*)d_in[0];
    const int*   lab32 = (const int*)d_in[1];
    const float* W     = (const float*)d_in[2];
    float* out = (float*)d_out;

    cudaFuncSetAttribute(k_gemm, cudaFuncAttributeMaxDynamicSharedMemorySize, DSMEM);

    k_prep<<<NWB + NEB + 1, 256>>>(W, emb, lab32);
    k_gemm<<<dim3(NCB, B_ROWS / BM), 256, DSMEM>>>();
    k_rows<<<B_ROWS / 8, 256>>>(out);
}